// round 5
// baseline (speedup 1.0000x reference)
#include <cuda_runtime.h>
#include <cstdint>
#include <math.h>

#define MTOK 32768
#define DIN  512
#define DCC  256
#define NQ   8
#define NB   1024
#define OUTE (MTOK*DIN)
#define IDXE (NQ*MTOK)

typedef unsigned long long u64;

// ---------------------------------------------------------------------------
// Device scratch (allocation-free rule: __device__ globals)
// ---------------------------------------------------------------------------
__device__ float g_res[MTOK*DCC];     // residual, init = h (exact fp32)
__device__ float g_quant[MTOK*DCC];   // running quantized sum (exact fp32)
__device__ float g_e2h[NQ*NB];        // ||e||^2 per codeword
__device__ float g_idxf[IDXE];        // idx sink when d_out has no idx region
__device__ float g_cpart[NQ*512];     // per-block commit partial sums

// ---------------------------------------------------------------------------
// XLA fast-tanh (rational approx; matches jnp.tanh GPU lowering)
// ---------------------------------------------------------------------------
__device__ __forceinline__ float xla_tanh(float x){
  float xc = fminf(fmaxf(x, -7.90531110763549805f), 7.90531110763549805f);
  float x2 = xc*xc;
  float p = __fmaf_rn(x2, -2.76076847742355e-16f, 2.00018790482477e-13f);
  p = __fmaf_rn(x2, p, -8.60467152213735e-11f);
  p = __fmaf_rn(x2, p,  5.12229709037114e-08f);
  p = __fmaf_rn(x2, p,  1.48572235717979e-05f);
  p = __fmaf_rn(x2, p,  6.37261928875436e-04f);
  p = __fmaf_rn(x2, p,  4.89352455891786e-03f);
  p = xc*p;
  float q = __fmaf_rn(x2, 1.19825839466702e-06f, 1.18534705686654e-04f);
  q = __fmaf_rn(x2, q, 2.26843463243900e-03f);
  q = __fmaf_rn(x2, q, 4.89352518554385e-03f);
  float r = __fdiv_rn(p, q);
  return (fabsf(x) < 0.0004f) ? x : r;
}

// ---------------------------------------------------------------------------
// Packed f32x2 helpers (Blackwell FFMA2: 2x fp32 FMA throughput).
// Packing is along N (bin pairs): each fp32 component is an independent
// strictly k-sequential FFMA chain -> bitwise == scalar serial-k fp32.
// ---------------------------------------------------------------------------
__device__ __forceinline__ u64 pk2(float lo, float hi){
  u64 r; asm("mov.b64 %0,{%1,%2};" : "=l"(r) : "f"(lo), "f"(hi)); return r;
}
__device__ __forceinline__ void upk2(u64 v, float& lo, float& hi){
  asm("mov.b64 {%0,%1},%2;" : "=f"(lo), "=f"(hi) : "l"(v));
}
__device__ __forceinline__ u64 ff2(u64 a, u64 b, u64 c){
  u64 d; asm("fma.rn.f32x2 %0,%1,%2,%3;" : "=l"(d) : "l"(a), "l"(b), "l"(c));
  return d;
}

// ---------------------------------------------------------------------------
// Shared-tile helpers. A tile stored pre-duplicated (a,a) pairs; B tile
// stored transposed [k][n] (pad 132) for contiguous LDS.64 col-pairs.
// ---------------------------------------------------------------------------
__device__ __forceinline__ void stsA(u64 (*As)[16], int lr, int lq, float4 ra){
  As[lr][lq*4+0] = pk2(ra.x, ra.x);
  As[lr][lq*4+1] = pk2(ra.y, ra.y);
  As[lr][lq*4+2] = pk2(ra.z, ra.z);
  As[lr][lq*4+3] = pk2(ra.w, ra.w);
}
__device__ __forceinline__ void stsB(float (*Bs)[132], int lr, int lq,
                                     float4 rb0, float4 rb1){
  Bs[lq*4+0][lr]    = rb0.x; Bs[lq*4+1][lr]    = rb0.y;
  Bs[lq*4+2][lr]    = rb0.z; Bs[lq*4+3][lr]    = rb0.w;
  Bs[lq*4+0][64+lr] = rb1.x; Bs[lq*4+1][64+lr] = rb1.y;
  Bs[lq*4+2][64+lr] = rb1.z; Bs[lq*4+3][64+lr] = rb1.w;
}
// 16 k-steps of 4 rows x 4 packed col-pairs FFMA2 per thread
__device__ __forceinline__ void mm16(const u64 (*As)[16], const float (*Bs)[132],
                                     int tx, int ty, u64 c[4][4]){
  #pragma unroll
  for(int kk=0; kk<16; kk++){
    u64 a[4], b[4];
    #pragma unroll
    for(int i=0;i<4;i++) a[i] = As[ty*4+i][kk];
    #pragma unroll
    for(int j=0;j<4;j++) b[j] = *(const u64*)&Bs[kk][tx*8+2*j];
    #pragma unroll
    for(int i=0;i<4;i++)
      #pragma unroll
      for(int j=0;j<4;j++) c[i][j] = ff2(a[i], b[j], c[i][j]);
  }
}

// ---------------------------------------------------------------------------
// ||e||^2 per codeword: XLA row-reduce shape (stride-32 serial + shfl tree)
// ---------------------------------------------------------------------------
__global__ void e2_kernel(const float* __restrict__ cb){
  int bin  = blockIdx.x*8 + (threadIdx.x>>5);
  int lane = threadIdx.x & 31;
  const float* row = cb + (size_t)bin*DCC;
  float s = 0.f;
  #pragma unroll
  for(int i=0;i<8;i++){ float v = row[lane + 32*i]; s += v*v; }
  #pragma unroll
  for(int o=16;o;o>>=1) s += __shfl_down_sync(0xffffffffu, s, o);
  if(!lane) g_e2h[bin] = s;
}

// ---------------------------------------------------------------------------
// C[m,n] = act(sum_k A[m,k]*B[n,k] + bias[n]); exact fp32, serial-k chain.
// mode 1: A=Ain(x), C=g_res with xla_tanh, also zero g_quant.
// mode 0: A=g_quant, C=Cin (final out).
// ---------------------------------------------------------------------------
__global__ __launch_bounds__(256,2) void gemm_kernel(
    const float* __restrict__ Ain, const float* __restrict__ B,
    const float* __restrict__ bias, float* __restrict__ Cin,
    int N, int K, int mode)
{
  __shared__ u64 As[2][64][16];
  __shared__ __align__(16) float Bs[2][16][132];

  const float* A = (mode==1) ? Ain : g_quant;
  float*       C = (mode==1) ? g_res : Cin;

  int tid = threadIdx.x, tx = tid & 15, ty = tid >> 4;
  int rowbase = blockIdx.x*64, colbase = blockIdx.y*128;
  int lr = tid >> 2, lq = tid & 3;

  const float* Aload  = A + (size_t)(rowbase+lr)*K + lq*4;
  const float* Bload0 = B + (size_t)(colbase+lr)*K + lq*4;
  const float* Bload1 = B + (size_t)(colbase+64+lr)*K + lq*4;

  u64 c[4][4];
  #pragma unroll
  for(int i=0;i<4;i++)
    #pragma unroll
    for(int j=0;j<4;j++) c[i][j] = 0ull;

  int NS = K >> 4;
  float4 ra  = *(const float4*)(Aload);
  float4 rb0 = *(const float4*)(Bload0);
  float4 rb1 = *(const float4*)(Bload1);
  stsA(As[0], lr, lq, ra);
  stsB(Bs[0], lr, lq, rb0, rb1);
  __syncthreads();

  for(int s=0; s<NS; s++){
    int buf = s & 1;
    if(s+1 < NS){
      ra  = *(const float4*)(Aload  + (s+1)*16);
      rb0 = *(const float4*)(Bload0 + (s+1)*16);
      rb1 = *(const float4*)(Bload1 + (s+1)*16);
    }
    mm16(As[buf], Bs[buf], tx, ty, c);
    if(s+1 < NS){
      stsA(As[buf^1], lr, lq, ra);
      stsB(Bs[buf^1], lr, lq, rb0, rb1);
    }
    __syncthreads();
  }

  #pragma unroll
  for(int i=0;i<4;i++){
    int row = rowbase + ty*4 + i;
    #pragma unroll
    for(int j=0;j<4;j++){
      int col = colbase + tx*8 + 2*j;
      float lo, hi; upk2(c[i][j], lo, hi);
      lo += bias[col]; hi += bias[col+1];
      if(mode==1){ lo = xla_tanh(lo); hi = xla_tanh(hi); }
      float2 v; v.x = lo; v.y = hi;
      *(float2*)&C[(size_t)row*N + col] = v;
      if(mode==1){
        float2 z; z.x = 0.f; z.y = 0.f;
        *(float2*)&g_quant[(size_t)row*N + col] = z;
      }
    }
  }
}

// ---------------------------------------------------------------------------
// One RVQ stage: dot = serial-k fp32 chain; dist = fl(fl(r2 - 2*dot) + e2)
// exactly like the reference expression tree; argmin = first-min index;
// gather codeword, update residual/quant, commit partial.
// ---------------------------------------------------------------------------
__global__ __launch_bounds__(256,2) void stage_kernel(
    const float* __restrict__ cbr,  // this stage's codebook [NB][DCC]
    float* __restrict__ idxdst,     // may be nullptr -> internal sink
    int stage)
{
  __shared__ u64 As[2][64][16];
  __shared__ __align__(16) float Bs[2][16][132];
  __shared__ float e2s[NB];
  __shared__ float r2s[64];
  __shared__ int   sidx[64];
  __shared__ float sred[8];

  int tid = threadIdx.x, tx = tid & 15, ty = tid >> 4;
  int rowbase = blockIdx.x*64;
  int lr = tid >> 2, lq = tid & 3;
  int wid = tid >> 5, lane = tid & 31;

  for(int i=tid; i<NB; i+=256) e2s[i] = g_e2h[stage*NB + i];

  // r2 per token: XLA row-reduce shape (stride-32 serial + shfl_down tree)
  for(int rr=0; rr<8; rr++){
    int row = wid*8 + rr;
    const float* rp = g_res + (size_t)(rowbase+row)*DCC;
    float s = 0.f;
    #pragma unroll
    for(int i=0;i<8;i++){ float v = rp[lane+32*i]; s += v*v; }
    #pragma unroll
    for(int o=16;o;o>>=1) s += __shfl_down_sync(0xffffffffu, s, o);
    if(!lane) r2s[row] = s;
  }

  const float* Aload = g_res + (size_t)(rowbase+lr)*DCC + lq*4;

  float rbv[4]; int rbi[4];
  #pragma unroll
  for(int i=0;i<4;i++){ rbv[i] = 3.402823466e38f; rbi[i] = 0x7fffffff; }

  __syncthreads();   // e2s + r2s ready

  for(int ch=0; ch<8; ch++){
    int colbase = ch*128;
    const float* Bload0 = cbr + (size_t)(colbase+lr)*DCC + lq*4;
    const float* Bload1 = cbr + (size_t)(colbase+64+lr)*DCC + lq*4;

    u64 c[4][4];
    #pragma unroll
    for(int i=0;i<4;i++)
      #pragma unroll
      for(int j=0;j<4;j++) c[i][j] = 0ull;

    float4 ra  = *(const float4*)(Aload);
    float4 rb0 = *(const float4*)(Bload0);
    float4 rb1 = *(const float4*)(Bload1);
    stsA(As[0], lr, lq, ra);
    stsB(Bs[0], lr, lq, rb0, rb1);
    __syncthreads();

    for(int s=0; s<16; s++){          // 16 K-slices of 16 (K=256)
      int buf = s & 1;
      if(s+1 < 16){
        ra  = *(const float4*)(Aload  + (s+1)*16);
        rb0 = *(const float4*)(Bload0 + (s+1)*16);
        rb1 = *(const float4*)(Bload1 + (s+1)*16);
      }
      mm16(As[buf], Bs[buf], tx, ty, c);
      if(s+1 < 16){
        stsA(As[buf^1], lr, lq, ra);
        stsB(Bs[buf^1], lr, lq, rb0, rb1);
      }
      __syncthreads();
    }

    // per-row argmin over this chunk's 128 bins, reference rounding order
    #pragma unroll
    for(int i=0;i<4;i++){
      float r2v = r2s[ty*4+i];
      float bv = 3.402823466e38f; int bi = 0x7fffffff;
      #pragma unroll
      for(int j=0;j<4;j++){
        float lo, hi; upk2(c[i][j], lo, hi);
        int col0 = colbase + tx*8 + 2*j;
        float dlo = (r2v - 2.0f*lo) + e2s[col0];
        float dhi = (r2v - 2.0f*hi) + e2s[col0+1];
        if(dlo < bv){ bv = dlo; bi = col0; }
        if(dhi < bv){ bv = dhi; bi = col0+1; }
      }
      #pragma unroll
      for(int o=8;o;o>>=1){
        float ov = __shfl_xor_sync(0xffffffffu, bv, o);
        int   oi = __shfl_xor_sync(0xffffffffu, bi, o);
        if(ov < bv || (ov == bv && oi < bi)){ bv = ov; bi = oi; }
      }
      if(bv < rbv[i] || (bv == rbv[i] && bi < rbi[i])){ rbv[i] = bv; rbi[i] = bi; }
    }
  }

  float* ip = idxdst ? idxdst : g_idxf;
  if(tx == 0){
    #pragma unroll
    for(int i=0;i<4;i++){
      int row = ty*4 + i;
      sidx[row] = rbi[i];
      ip[(size_t)stage*MTOK + rowbase + row] = (float)rbi[i];
    }
  }
  __syncthreads();

  // update phase: 4 threads per token, 64 cols each
  float loc = 0.f;
  {
    int row = tid >> 2, seg = tid & 3;
    int bin = sidx[row];
    const float4* q4 = (const float4*)(cbr + (size_t)bin*DCC + seg*64);
    float4* r4  = (float4*)(g_res   + (size_t)(rowbase+row)*DCC + seg*64);
    float4* qt4 = (float4*)(g_quant + (size_t)(rowbase+row)*DCC + seg*64);
    #pragma unroll
    for(int i=0;i<16;i++){
      float4 q = q4[i], r = r4[i], qt = qt4[i];
      float4 nr; nr.x=r.x-q.x; nr.y=r.y-q.y; nr.z=r.z-q.z; nr.w=r.w-q.w;
      r4[i] = nr;
      float4 nq; nq.x=qt.x+q.x; nq.y=qt.y+q.y; nq.z=qt.z+q.z; nq.w=qt.w+q.w;
      qt4[i] = nq;
      loc += nr.x*nr.x + nr.y*nr.y + nr.z*nr.z + nr.w*nr.w;
    }
  }
  #pragma unroll
  for(int o=16;o;o>>=1) loc += __shfl_xor_sync(0xffffffffu, loc, o);
  if(!lane) sred[wid] = loc;
  __syncthreads();
  if(tid < 8){
    float v = sred[tid];
    #pragma unroll
    for(int o=4;o;o>>=1) v += __shfl_xor_sync(0xffu, v, o);
    if(!tid) g_cpart[stage*512 + blockIdx.x] = v;
  }
}

// ---------------------------------------------------------------------------
__global__ void finalize_kernel(float* __restrict__ loss_dst){
  __shared__ float sr[512];
  int t = threadIdx.x;
  float s = 0.f;
  for(int k=t; k<NQ*512; k+=512) s += g_cpart[k];
  sr[t] = s; __syncthreads();
  for(int o=256;o;o>>=1){ if(t<o) sr[t]+=sr[t+o]; __syncthreads(); }
  if(!t) *loss_dst = 0.1f * sr[0] * (1.0f/((float)MTOK*(float)DCC));
}

__global__ void fill_kernel(float* __restrict__ p, int n){
  int i = blockIdx.x*256 + threadIdx.x;
  if(i < n) p[i] = 0.f;
}

// ---------------------------------------------------------------------------
extern "C" void kernel_launch(void* const* d_in, const int* in_sizes, int n_in,
                              void* d_out, int out_size){
  const float* x     = (const float*)d_in[0];
  const float* in_w  = (const float*)d_in[1];
  const float* in_b  = (const float*)d_in[2];
  const float* out_w = (const float*)d_in[3];
  const float* out_b = (const float*)d_in[4];
  const float* cb    = (const float*)d_in[5];
  float* out = (float*)d_out;

  if(out_size < OUTE){
    if(out_size > 0)
      fill_kernel<<<(out_size + 255)/256, 256>>>(out, out_size);
    return;
  }

  e2_kernel<<<NQ*NB/8, 256>>>(cb);

  gemm_kernel<<<dim3(MTOK/64, DCC/128), 256>>>(x, in_w, in_b, nullptr,
                                               DCC, DIN, 1);

  float* idxdst = (out_size >= OUTE + IDXE) ? (out + OUTE) : nullptr;
  for(int s=0; s<NQ; s++)
    stage_kernel<<<MTOK/64, 256>>>(cb + (size_t)s*NB*DCC, idxdst, s);

  gemm_kernel<<<dim3(MTOK/64, DIN/128), 256>>>(nullptr, out_w, out_b, out,
                                               DIN, DCC, 0);

  int written = OUTE;
  if(out_size >= OUTE + IDXE) written = OUTE + IDXE;
  if(out_size > written){
    finalize_kernel<<<1, 512>>>(out + written);
    written += 1;
  }
  if(out_size > written){
    int n = out_size - written;
    fill_kernel<<<(n + 255)/256, 256>>>(out + written, n);
  }
}

// round 8
// speedup vs baseline: 1.4569x; 1.4569x over previous
#include <cuda_runtime.h>
#include <cstdint>
#include <math.h>

#define MTOK 32768
#define DIN  512
#define DCC  256
#define NQ   8
#define NB   1024
#define OUTE (MTOK*DIN)
#define IDXE (NQ*MTOK)

typedef unsigned long long u64;

// ---------------------------------------------------------------------------
// Device scratch (allocation-free rule: __device__ globals)
// ---------------------------------------------------------------------------
__device__ float g_res[MTOK*DCC];     // residual, init = h (exact fp32)
__device__ float g_quant[MTOK*DCC];   // running quantized sum (exact fp32)
__device__ float g_e2h[NQ*NB];        // ||e||^2 per codeword
__device__ float g_idxf[IDXE];        // idx sink when d_out has no idx region
__device__ float g_cpart[NQ*512];     // per-block commit partial sums

// ---------------------------------------------------------------------------
// XLA fast-tanh (rational approx; matches jnp.tanh GPU lowering)
// ---------------------------------------------------------------------------
__device__ __forceinline__ float xla_tanh(float x){
  float xc = fminf(fmaxf(x, -7.90531110763549805f), 7.90531110763549805f);
  float x2 = xc*xc;
  float p = __fmaf_rn(x2, -2.76076847742355e-16f, 2.00018790482477e-13f);
  p = __fmaf_rn(x2, p, -8.60467152213735e-11f);
  p = __fmaf_rn(x2, p,  5.12229709037114e-08f);
  p = __fmaf_rn(x2, p,  1.48572235717979e-05f);
  p = __fmaf_rn(x2, p,  6.37261928875436e-04f);
  p = __fmaf_rn(x2, p,  4.89352455891786e-03f);
  p = xc*p;
  float q = __fmaf_rn(x2, 1.19825839466702e-06f, 1.18534705686654e-04f);
  q = __fmaf_rn(x2, q, 2.26843463243900e-03f);
  q = __fmaf_rn(x2, q, 4.89352518554385e-03f);
  float r = __fdiv_rn(p, q);
  return (fabsf(x) < 0.0004f) ? x : r;
}

// ---------------------------------------------------------------------------
// Packed f32x2 helpers. Each fp32 component is an independent strictly
// k-sequential FFMA chain -> bitwise == scalar serial-k fp32.
// ---------------------------------------------------------------------------
__device__ __forceinline__ u64 pk2(float lo, float hi){
  u64 r; asm("mov.b64 %0,{%1,%2};" : "=l"(r) : "f"(lo), "f"(hi)); return r;
}
__device__ __forceinline__ void upk2(u64 v, float& lo, float& hi){
  asm("mov.b64 {%0,%1},%2;" : "=f"(lo), "=f"(hi) : "l"(v));
}
__device__ __forceinline__ u64 ff2(u64 a, u64 b, u64 c){
  u64 d; asm("fma.rn.f32x2 %0,%1,%2,%3;" : "=l"(d) : "l"(a), "l"(b), "l"(c));
  return d;
}

// ---------------------------------------------------------------------------
// Shared tiles.
//  A: [64][17] u64 (17-pad -> warp's two distinct row addresses hit
//     different banks; each is a 16-lane broadcast -> 1 phase per LDS.64)
//  B: transposed [k][132 floats]; thread fragments at cols
//     {tx*4, tx*4+2, tx*4+64, tx*4+66} -> two LDS.128 at 16B stride,
//     conflict-free, dedup across half-warps.
// ---------------------------------------------------------------------------
__device__ __forceinline__ void stsA(u64 (*As)[17], int lr, int lq, float4 ra){
  As[lr][lq*4+0] = pk2(ra.x, ra.x);
  As[lr][lq*4+1] = pk2(ra.y, ra.y);
  As[lr][lq*4+2] = pk2(ra.z, ra.z);
  As[lr][lq*4+3] = pk2(ra.w, ra.w);
}
__device__ __forceinline__ void stsB(float (*Bs)[132], int lr, int lq,
                                     float4 rb0, float4 rb1){
  Bs[lq*4+0][lr]    = rb0.x; Bs[lq*4+1][lr]    = rb0.y;
  Bs[lq*4+2][lr]    = rb0.z; Bs[lq*4+3][lr]    = rb0.w;
  Bs[lq*4+0][64+lr] = rb1.x; Bs[lq*4+1][64+lr] = rb1.y;
  Bs[lq*4+2][64+lr] = rb1.z; Bs[lq*4+3][64+lr] = rb1.w;
}
// 16 k-steps of 4 rows x 4 packed col-pairs FFMA2 per thread
__device__ __forceinline__ void mm16(const u64 (*As)[17], const float (*Bs)[132],
                                     int tx, int ty, u64 c[4][4]){
  #pragma unroll
  for(int kk=0; kk<16; kk++){
    u64 a[4];
    #pragma unroll
    for(int i=0;i<4;i++) a[i] = As[ty*4+i][kk];
    ulonglong2 b01 = *(const ulonglong2*)&Bs[kk][tx*4];
    ulonglong2 b23 = *(const ulonglong2*)&Bs[kk][tx*4+64];
    u64 b[4]; b[0]=b01.x; b[1]=b01.y; b[2]=b23.x; b[3]=b23.y;
    #pragma unroll
    for(int i=0;i<4;i++)
      #pragma unroll
      for(int j=0;j<4;j++) c[i][j] = ff2(a[i], b[j], c[i][j]);
  }
}
// fragment j -> column offset within the 128-col chunk
__device__ __forceinline__ int fcol(int tx, int j){
  return tx*4 + (j&1)*2 + (j>>1)*64;
}

// ---------------------------------------------------------------------------
// ||e||^2 per codeword: XLA row-reduce shape (stride-32 serial + shfl tree)
// ---------------------------------------------------------------------------
__global__ void e2_kernel(const float* __restrict__ cb){
  int bin  = blockIdx.x*8 + (threadIdx.x>>5);
  int lane = threadIdx.x & 31;
  const float* row = cb + (size_t)bin*DCC;
  float s = 0.f;
  #pragma unroll
  for(int i=0;i<8;i++){ float v = row[lane + 32*i]; s += v*v; }
  #pragma unroll
  for(int o=16;o;o>>=1) s += __shfl_down_sync(0xffffffffu, s, o);
  if(!lane) g_e2h[bin] = s;
}

// ---------------------------------------------------------------------------
// C[m,n] = act(sum_k A[m,k]*B[n,k] + bias[n]); exact fp32, serial-k chain.
// mode 1: A=Ain(x), C=g_res with xla_tanh, also zero g_quant.
// mode 0: A=g_quant, C=Cin (final out).
// ---------------------------------------------------------------------------
__global__ __launch_bounds__(256,2) void gemm_kernel(
    const float* __restrict__ Ain, const float* __restrict__ B,
    const float* __restrict__ bias, float* __restrict__ Cin,
    int N, int K, int mode)
{
  __shared__ u64 As[2][64][17];
  __shared__ __align__(16) float Bs[2][16][132];

  const float* A = (mode==1) ? Ain : g_quant;
  float*       C = (mode==1) ? g_res : Cin;

  int tid = threadIdx.x, tx = tid & 15, ty = tid >> 4;
  int rowbase = blockIdx.x*64, colbase = blockIdx.y*128;
  int lr = tid >> 2, lq = tid & 3;

  const float* Aload  = A + (size_t)(rowbase+lr)*K + lq*4;
  const float* Bload0 = B + (size_t)(colbase+lr)*K + lq*4;
  const float* Bload1 = B + (size_t)(colbase+64+lr)*K + lq*4;

  u64 c[4][4];
  #pragma unroll
  for(int i=0;i<4;i++)
    #pragma unroll
    for(int j=0;j<4;j++) c[i][j] = 0ull;

  int NS = K >> 4;
  float4 ra  = *(const float4*)(Aload);
  float4 rb0 = *(const float4*)(Bload0);
  float4 rb1 = *(const float4*)(Bload1);
  stsA(As[0], lr, lq, ra);
  stsB(Bs[0], lr, lq, rb0, rb1);
  __syncthreads();

  for(int s=0; s<NS; s++){
    int buf = s & 1;
    if(s+1 < NS){
      ra  = *(const float4*)(Aload  + (s+1)*16);
      rb0 = *(const float4*)(Bload0 + (s+1)*16);
      rb1 = *(const float4*)(Bload1 + (s+1)*16);
    }
    mm16(As[buf], Bs[buf], tx, ty, c);
    if(s+1 < NS){
      stsA(As[buf^1], lr, lq, ra);
      stsB(Bs[buf^1], lr, lq, rb0, rb1);
    }
    __syncthreads();
  }

  #pragma unroll
  for(int i=0;i<4;i++){
    int row = rowbase + ty*4 + i;
    #pragma unroll
    for(int h=0; h<2; h++){          // h=0: frags 0,1 ; h=1: frags 2,3
      int col = colbase + tx*4 + h*64;
      float4 bb = *(const float4*)&bias[col];
      float l0, h0, l1, h1;
      upk2(c[i][2*h+0], l0, h0);
      upk2(c[i][2*h+1], l1, h1);
      float4 v;
      v.x = l0 + bb.x; v.y = h0 + bb.y; v.z = l1 + bb.z; v.w = h1 + bb.w;
      if(mode==1){
        v.x = xla_tanh(v.x); v.y = xla_tanh(v.y);
        v.z = xla_tanh(v.z); v.w = xla_tanh(v.w);
      }
      *(float4*)&C[(size_t)row*N + col] = v;
      if(mode==1){
        float4 z; z.x=0.f; z.y=0.f; z.z=0.f; z.w=0.f;
        *(float4*)&g_quant[(size_t)row*N + col] = z;
      }
    }
  }
}

// ---------------------------------------------------------------------------
// One RVQ stage: dot = serial-k fp32 chain; dist = fl(fl(r2 - 2*dot) + e2)
// exactly like the reference expression tree; argmin = first-min index;
// gather codeword, update residual/quant, commit partial.
// ---------------------------------------------------------------------------
__global__ __launch_bounds__(256,2) void stage_kernel(
    const float* __restrict__ cbr,  // this stage's codebook [NB][DCC]
    float* __restrict__ idxdst,     // may be nullptr -> internal sink
    int stage)
{
  __shared__ u64 As[2][64][17];
  __shared__ __align__(16) float Bs[2][16][132];
  __shared__ float e2s[NB];
  __shared__ float r2s[64];
  __shared__ int   sidx[64];
  __shared__ float sred[8];

  int tid = threadIdx.x, tx = tid & 15, ty = tid >> 4;
  int rowbase = blockIdx.x*64;
  int lr = tid >> 2, lq = tid & 3;
  int wid = tid >> 5, lane = tid & 31;

  for(int i=tid; i<NB; i+=256) e2s[i] = g_e2h[stage*NB + i];

  // r2 per token: XLA row-reduce shape (stride-32 serial + shfl_down tree)
  for(int rr=0; rr<8; rr++){
    int row = wid*8 + rr;
    const float* rp = g_res + (size_t)(rowbase+row)*DCC;
    float s = 0.f;
    #pragma unroll
    for(int i=0;i<8;i++){ float v = rp[lane+32*i]; s += v*v; }
    #pragma unroll
    for(int o=16;o;o>>=1) s += __shfl_down_sync(0xffffffffu, s, o);
    if(!lane) r2s[row] = s;
  }

  const float* Aload = g_res + (size_t)(rowbase+lr)*DCC + lq*4;

  float rbv[4]; int rbi[4];
  #pragma unroll
  for(int i=0;i<4;i++){ rbv[i] = 3.402823466e38f; rbi[i] = 0x7fffffff; }

  __syncthreads();   // e2s + r2s ready

  for(int ch=0; ch<8; ch++){
    int colbase = ch*128;
    const float* Bload0 = cbr + (size_t)(colbase+lr)*DCC + lq*4;
    const float* Bload1 = cbr + (size_t)(colbase+64+lr)*DCC + lq*4;

    u64 c[4][4];
    #pragma unroll
    for(int i=0;i<4;i++)
      #pragma unroll
      for(int j=0;j<4;j++) c[i][j] = 0ull;

    float4 ra  = *(const float4*)(Aload);
    float4 rb0 = *(const float4*)(Bload0);
    float4 rb1 = *(const float4*)(Bload1);
    stsA(As[0], lr, lq, ra);
    stsB(Bs[0], lr, lq, rb0, rb1);
    __syncthreads();

    for(int s=0; s<16; s++){          // 16 K-slices of 16 (K=256)
      int buf = s & 1;
      if(s+1 < 16){
        ra  = *(const float4*)(Aload  + (s+1)*16);
        rb0 = *(const float4*)(Bload0 + (s+1)*16);
        rb1 = *(const float4*)(Bload1 + (s+1)*16);
      }
      mm16(As[buf], Bs[buf], tx, ty, c);
      if(s+1 < 16){
        stsA(As[buf^1], lr, lq, ra);
        stsB(Bs[buf^1], lr, lq, rb0, rb1);
      }
      __syncthreads();
    }

    // per-row argmin over this chunk's 128 bins, reference rounding order
    #pragma unroll
    for(int i=0;i<4;i++){
      float r2v = r2s[ty*4+i];
      float bv = 3.402823466e38f; int bi = 0x7fffffff;
      #pragma unroll
      for(int j=0;j<4;j++){
        float lo, hi; upk2(c[i][j], lo, hi);
        int col0 = colbase + fcol(tx, j);
        float dlo = (r2v - 2.0f*lo) + e2s[col0];
        float dhi = (r2v - 2.0f*hi) + e2s[col0+1];
        if(dlo < bv){ bv = dlo; bi = col0; }
        if(dhi < bv){ bv = dhi; bi = col0+1; }
      }
      #pragma unroll
      for(int o=8;o;o>>=1){
        float ov = __shfl_xor_sync(0xffffffffu, bv, o);
        int   oi = __shfl_xor_sync(0xffffffffu, bi, o);
        if(ov < bv || (ov == bv && oi < bi)){ bv = ov; bi = oi; }
      }
      if(bv < rbv[i] || (bv == rbv[i] && bi < rbi[i])){ rbv[i] = bv; rbi[i] = bi; }
    }
  }

  float* ip = idxdst ? idxdst : g_idxf;
  if(tx == 0){
    #pragma unroll
    for(int i=0;i<4;i++){
      int row = ty*4 + i;
      sidx[row] = rbi[i];
      ip[(size_t)stage*MTOK + rowbase + row] = (float)rbi[i];
    }
  }
  __syncthreads();

  // update phase: 4 threads per token, 64 cols each
  float loc = 0.f;
  {
    int row = tid >> 2, seg = tid & 3;
    int bin = sidx[row];
    const float4* q4 = (const float4*)(cbr + (size_t)bin*DCC + seg*64);
    float4* r4  = (float4*)(g_res   + (size_t)(rowbase+row)*DCC + seg*64);
    float4* qt4 = (float4*)(g_quant + (size_t)(rowbase+row)*DCC + seg*64);
    #pragma unroll
    for(int i=0;i<16;i++){
      float4 q = q4[i], r = r4[i], qt = qt4[i];
      float4 nr; nr.x=r.x-q.x; nr.y=r.y-q.y; nr.z=r.z-q.z; nr.w=r.w-q.w;
      r4[i] = nr;
      float4 nq; nq.x=qt.x+q.x; nq.y=qt.y+q.y; nq.z=qt.z+q.z; nq.w=qt.w+q.w;
      qt4[i] = nq;
      loc += nr.x*nr.x + nr.y*nr.y + nr.z*nr.z + nr.w*nr.w;
    }
  }
  #pragma unroll
  for(int o=16;o;o>>=1) loc += __shfl_xor_sync(0xffffffffu, loc, o);
  if(!lane) sred[wid] = loc;
  __syncthreads();
  if(tid < 8){
    float v = sred[tid];
    #pragma unroll
    for(int o=4;o;o>>=1) v += __shfl_xor_sync(0xffu, v, o);
    if(!tid) g_cpart[stage*512 + blockIdx.x] = v;
  }
}

// ---------------------------------------------------------------------------
__global__ void finalize_kernel(float* __restrict__ loss_dst){
  __shared__ float sr[512];
  int t = threadIdx.x;
  float s = 0.f;
  for(int k=t; k<NQ*512; k+=512) s += g_cpart[k];
  sr[t] = s; __syncthreads();
  for(int o=256;o;o>>=1){ if(t<o) sr[t]+=sr[t+o]; __syncthreads(); }
  if(!t) *loss_dst = 0.1f * sr[0] * (1.0f/((float)MTOK*(float)DCC));
}

__global__ void fill_kernel(float* __restrict__ p, int n){
  int i = blockIdx.x*256 + threadIdx.x;
  if(i < n) p[i] = 0.f;
}

// ---------------------------------------------------------------------------
extern "C" void kernel_launch(void* const* d_in, const int* in_sizes, int n_in,
                              void* d_out, int out_size){
  const float* x     = (const float*)d_in[0];
  const float* in_w  = (const float*)d_in[1];
  const float* in_b  = (const float*)d_in[2];
  const float* out_w = (const float*)d_in[3];
  const float* out_b = (const float*)d_in[4];
  const float* cb    = (const float*)d_in[5];
  float* out = (float*)d_out;

  if(out_size < OUTE){
    if(out_size > 0)
      fill_kernel<<<(out_size + 255)/256, 256>>>(out, out_size);
    return;
  }

  e2_kernel<<<NQ*NB/8, 256>>>(cb);

  gemm_kernel<<<dim3(MTOK/64, DCC/128), 256>>>(x, in_w, in_b, nullptr,
                                               DCC, DIN, 1);

  float* idxdst = (out_size >= OUTE + IDXE) ? (out + OUTE) : nullptr;
  for(int s=0; s<NQ; s++)
    stage_kernel<<<MTOK/64, 256>>>(cb + (size_t)s*NB*DCC, idxdst, s);

  gemm_kernel<<<dim3(MTOK/64, DIN/128), 256>>>(nullptr, out_w, out_b, out,
                                               DIN, DCC, 0);

  int written = OUTE;
  if(out_size >= OUTE + IDXE) written = OUTE + IDXE;
  if(out_size > written){
    finalize_kernel<<<1, 512>>>(out + written);
    written += 1;
  }
  if(out_size > written){
    int n = out_size - written;
    fill_kernel<<<(n + 255)/256, 256>>>(out + written, n);
  }
}

// round 9
// speedup vs baseline: 1.5706x; 1.0780x over previous
#include <cuda_runtime.h>
#include <cstdint>
#include <math.h>

#define MTOK 32768
#define DIN  512
#define DCC  256
#define NQ   8
#define NB   1024
#define OUTE (MTOK*DIN)
#define IDXE (NQ*MTOK)

typedef unsigned long long u64;

// ---------------------------------------------------------------------------
// Device scratch (allocation-free rule: __device__ globals)
// ---------------------------------------------------------------------------
__device__ float g_res[MTOK*DCC];     // residual, init = h (exact fp32)
__device__ float g_quant[MTOK*DCC];   // running quantized sum (exact fp32)
__device__ float g_e2h[NQ*NB];        // ||e||^2 per codeword
__device__ float g_idxf[IDXE];        // idx sink when d_out has no idx region
__device__ float g_cpart[NQ*512];     // per-block commit partial sums

// ---------------------------------------------------------------------------
// XLA fast-tanh (rational approx; matches jnp.tanh GPU lowering)
// ---------------------------------------------------------------------------
__device__ __forceinline__ float xla_tanh(float x){
  float xc = fminf(fmaxf(x, -7.90531110763549805f), 7.90531110763549805f);
  float x2 = xc*xc;
  float p = __fmaf_rn(x2, -2.76076847742355e-16f, 2.00018790482477e-13f);
  p = __fmaf_rn(x2, p, -8.60467152213735e-11f);
  p = __fmaf_rn(x2, p,  5.12229709037114e-08f);
  p = __fmaf_rn(x2, p,  1.48572235717979e-05f);
  p = __fmaf_rn(x2, p,  6.37261928875436e-04f);
  p = __fmaf_rn(x2, p,  4.89352455891786e-03f);
  p = xc*p;
  float q = __fmaf_rn(x2, 1.19825839466702e-06f, 1.18534705686654e-04f);
  q = __fmaf_rn(x2, q, 2.26843463243900e-03f);
  q = __fmaf_rn(x2, q, 4.89352518554385e-03f);
  float r = __fdiv_rn(p, q);
  return (fabsf(x) < 0.0004f) ? x : r;
}

// ---------------------------------------------------------------------------
// Packed f32x2 helpers. Each fp32 component is an independent strictly
// k-sequential FFMA chain -> bitwise == scalar serial-k fp32.
// ---------------------------------------------------------------------------
__device__ __forceinline__ u64 pk2(float lo, float hi){
  u64 r; asm("mov.b64 %0,{%1,%2};" : "=l"(r) : "f"(lo), "f"(hi)); return r;
}
__device__ __forceinline__ void upk2(u64 v, float& lo, float& hi){
  asm("mov.b64 {%0,%1},%2;" : "=f"(lo), "=f"(hi) : "l"(v));
}
__device__ __forceinline__ u64 ff2(u64 a, u64 b, u64 c){
  u64 d; asm("fma.rn.f32x2 %0,%1,%2,%3;" : "=l"(d) : "l"(a), "l"(b), "l"(c));
  return d;
}

// ===========================================================================
// GEMM kernel (projections) — unchanged from the 5257us version
// ===========================================================================
__device__ __forceinline__ void stsA(u64 (*As)[17], int lr, int lq, float4 ra){
  As[lr][lq*4+0] = pk2(ra.x, ra.x);
  As[lr][lq*4+1] = pk2(ra.y, ra.y);
  As[lr][lq*4+2] = pk2(ra.z, ra.z);
  As[lr][lq*4+3] = pk2(ra.w, ra.w);
}
__device__ __forceinline__ void stsB(float (*Bs)[132], int lr, int lq,
                                     float4 rb0, float4 rb1){
  Bs[lq*4+0][lr]    = rb0.x; Bs[lq*4+1][lr]    = rb0.y;
  Bs[lq*4+2][lr]    = rb0.z; Bs[lq*4+3][lr]    = rb0.w;
  Bs[lq*4+0][64+lr] = rb1.x; Bs[lq*4+1][64+lr] = rb1.y;
  Bs[lq*4+2][64+lr] = rb1.z; Bs[lq*4+3][64+lr] = rb1.w;
}
__device__ __forceinline__ void mm16(const u64 (*As)[17], const float (*Bs)[132],
                                     int tx, int ty, u64 c[4][4]){
  #pragma unroll
  for(int kk=0; kk<16; kk++){
    u64 a[4];
    #pragma unroll
    for(int i=0;i<4;i++) a[i] = As[ty*4+i][kk];
    ulonglong2 b01 = *(const ulonglong2*)&Bs[kk][tx*4];
    ulonglong2 b23 = *(const ulonglong2*)&Bs[kk][tx*4+64];
    u64 b[4]; b[0]=b01.x; b[1]=b01.y; b[2]=b23.x; b[3]=b23.y;
    #pragma unroll
    for(int i=0;i<4;i++)
      #pragma unroll
      for(int j=0;j<4;j++) c[i][j] = ff2(a[i], b[j], c[i][j]);
  }
}

__global__ __launch_bounds__(256,2) void gemm_kernel(
    const float* __restrict__ Ain, const float* __restrict__ B,
    const float* __restrict__ bias, float* __restrict__ Cin,
    int N, int K, int mode)
{
  __shared__ u64 As[2][64][17];
  __shared__ __align__(16) float Bs[2][16][132];

  const float* A = (mode==1) ? Ain : g_quant;
  float*       C = (mode==1) ? g_res : Cin;

  int tid = threadIdx.x, tx = tid & 15, ty = tid >> 4;
  int rowbase = blockIdx.x*64, colbase = blockIdx.y*128;
  int lr = tid >> 2, lq = tid & 3;

  const float* Aload  = A + (size_t)(rowbase+lr)*K + lq*4;
  const float* Bload0 = B + (size_t)(colbase+lr)*K + lq*4;
  const float* Bload1 = B + (size_t)(colbase+64+lr)*K + lq*4;

  u64 c[4][4];
  #pragma unroll
  for(int i=0;i<4;i++)
    #pragma unroll
    for(int j=0;j<4;j++) c[i][j] = 0ull;

  int NS = K >> 4;
  float4 ra  = *(const float4*)(Aload);
  float4 rb0 = *(const float4*)(Bload0);
  float4 rb1 = *(const float4*)(Bload1);
  stsA(As[0], lr, lq, ra);
  stsB(Bs[0], lr, lq, rb0, rb1);
  __syncthreads();

  for(int s=0; s<NS; s++){
    int buf = s & 1;
    if(s+1 < NS){
      ra  = *(const float4*)(Aload  + (s+1)*16);
      rb0 = *(const float4*)(Bload0 + (s+1)*16);
      rb1 = *(const float4*)(Bload1 + (s+1)*16);
    }
    mm16(As[buf], Bs[buf], tx, ty, c);
    if(s+1 < NS){
      stsA(As[buf^1], lr, lq, ra);
      stsB(Bs[buf^1], lr, lq, rb0, rb1);
    }
    __syncthreads();
  }

  #pragma unroll
  for(int i=0;i<4;i++){
    int row = rowbase + ty*4 + i;
    #pragma unroll
    for(int h=0; h<2; h++){
      int col = colbase + tx*4 + h*64;
      float4 bb = *(const float4*)&bias[col];
      float l0, h0, l1, h1;
      upk2(c[i][2*h+0], l0, h0);
      upk2(c[i][2*h+1], l1, h1);
      float4 v;
      v.x = l0 + bb.x; v.y = h0 + bb.y; v.z = l1 + bb.z; v.w = h1 + bb.w;
      if(mode==1){
        v.x = xla_tanh(v.x); v.y = xla_tanh(v.y);
        v.z = xla_tanh(v.z); v.w = xla_tanh(v.w);
      }
      *(float4*)&C[(size_t)row*N + col] = v;
      if(mode==1){
        float4 z; z.x=0.f; z.y=0.f; z.z=0.f; z.w=0.f;
        *(float4*)&g_quant[(size_t)row*N + col] = z;
      }
    }
  }
}

// ---------------------------------------------------------------------------
// ||e||^2 per codeword: XLA row-reduce shape (stride-32 serial + shfl tree)
// ---------------------------------------------------------------------------
__global__ void e2_kernel(const float* __restrict__ cb){
  int bin  = blockIdx.x*8 + (threadIdx.x>>5);
  int lane = threadIdx.x & 31;
  const float* row = cb + (size_t)bin*DCC;
  float s = 0.f;
  #pragma unroll
  for(int i=0;i<8;i++){ float v = row[lane + 32*i]; s += v*v; }
  #pragma unroll
  for(int o=16;o;o>>=1) s += __shfl_down_sync(0xffffffffu, s, o);
  if(!lane) g_e2h[bin] = s;
}

// ===========================================================================
// Stage kernel: 128 tokens/block, thread tile 8 rows x 8 cols (4 u64 pairs).
// 3 B smem traffic per FFMA2 (was 4). k-slice = 8 (double-buffered).
// Accumulator chains strictly k-ascending fp32 (bit-identical to before).
// ===========================================================================
__device__ __forceinline__ void stsA2(u64 (*As)[9], int lr, int lq, float4 ra){
  As[lr][lq*4+0] = pk2(ra.x, ra.x);
  As[lr][lq*4+1] = pk2(ra.y, ra.y);
  As[lr][lq*4+2] = pk2(ra.z, ra.z);
  As[lr][lq*4+3] = pk2(ra.w, ra.w);
}
__device__ __forceinline__ void stsB2(float (*Bs)[132], int lr, int lq, float4 rb){
  Bs[lq*4+0][lr] = rb.x; Bs[lq*4+1][lr] = rb.y;
  Bs[lq*4+2][lr] = rb.z; Bs[lq*4+3][lr] = rb.w;
}
__device__ __forceinline__ void mm8(const u64 (*As)[9], const float (*Bs)[132],
                                    int tx, int ty, u64 c[8][4]){
  #pragma unroll
  for(int kk=0; kk<8; kk++){
    u64 a[8];
    #pragma unroll
    for(int i=0;i<8;i++) a[i] = As[ty*8+i][kk];
    ulonglong2 b01 = *(const ulonglong2*)&Bs[kk][tx*4];
    ulonglong2 b23 = *(const ulonglong2*)&Bs[kk][tx*4+64];
    u64 b[4]; b[0]=b01.x; b[1]=b01.y; b[2]=b23.x; b[3]=b23.y;
    #pragma unroll
    for(int i=0;i<8;i++)
      #pragma unroll
      for(int j=0;j<4;j++) c[i][j] = ff2(a[i], b[j], c[i][j]);
  }
}
__device__ __forceinline__ int fcol(int tx, int j){
  return tx*4 + (j&1)*2 + (j>>1)*64;
}

__global__ __launch_bounds__(256,2) void stage_kernel(
    const float* __restrict__ cbr,  // this stage's codebook [NB][DCC]
    float* __restrict__ idxdst,     // may be nullptr -> internal sink
    int stage)
{
  __shared__ u64 As[2][128][9];
  __shared__ __align__(16) float Bs[2][8][132];
  __shared__ float e2s[NB];
  __shared__ float r2s[128];
  __shared__ float sbv[128];
  __shared__ int   sidx[128];
  __shared__ float sred[8];

  int tid = threadIdx.x, tx = tid & 15, ty = tid >> 4;
  int rowbase = blockIdx.x*128;
  int lr = tid >> 1, lq = tid & 1;
  int wid = tid >> 5, lane = tid & 31;

  for(int i=tid; i<NB; i+=256) e2s[i] = g_e2h[stage*NB + i];
  if(tid < 128){ sbv[tid] = 3.402823466e38f; sidx[tid] = 0x7fffffff; }

  // r2 per token: XLA row-reduce shape (stride-32 serial + shfl_down tree)
  for(int rr=0; rr<16; rr++){
    int row = wid*16 + rr;
    const float* rp = g_res + (size_t)(rowbase+row)*DCC;
    float s = 0.f;
    #pragma unroll
    for(int i=0;i<8;i++){ float v = rp[lane+32*i]; s += v*v; }
    #pragma unroll
    for(int o=16;o;o>>=1) s += __shfl_down_sync(0xffffffffu, s, o);
    if(!lane) r2s[row] = s;
  }

  const float* Aload = g_res + (size_t)(rowbase+lr)*DCC + lq*4;

  __syncthreads();   // e2s + r2s + sbv ready

  for(int ch=0; ch<8; ch++){
    int colbase = ch*128;
    const float* Bload = cbr + (size_t)(colbase+lr)*DCC + lq*4;

    u64 c[8][4];
    #pragma unroll
    for(int i=0;i<8;i++)
      #pragma unroll
      for(int j=0;j<4;j++) c[i][j] = 0ull;

    float4 ra = *(const float4*)(Aload);
    float4 rb = *(const float4*)(Bload);
    stsA2(As[0], lr, lq, ra);
    stsB2(Bs[0], lr, lq, rb);
    __syncthreads();

    for(int s=0; s<32; s++){          // 32 K-slices of 8 (K=256)
      int buf = s & 1;
      if(s+1 < 32){
        ra = *(const float4*)(Aload + (s+1)*8);
        rb = *(const float4*)(Bload + (s+1)*8);
      }
      mm8(As[buf], Bs[buf], tx, ty, c);
      if(s+1 < 32){
        stsA2(As[buf^1], lr, lq, ra);
        stsB2(Bs[buf^1], lr, lq, rb);
      }
      __syncthreads();
    }

    // per-row argmin over this chunk's 128 bins, reference rounding order.
    // Running best lives in smem (single writer per row: tx==0 of each ty).
    #pragma unroll
    for(int i=0;i<8;i++){
      int row = ty*8 + i;
      float r2v = r2s[row];
      float bv = 3.402823466e38f; int bi = 0x7fffffff;
      #pragma unroll
      for(int j=0;j<4;j++){
        float lo, hi; upk2(c[i][j], lo, hi);
        int col0 = colbase + fcol(tx, j);
        float dlo = (r2v - 2.0f*lo) + e2s[col0];
        float dhi = (r2v - 2.0f*hi) + e2s[col0+1];
        if(dlo < bv){ bv = dlo; bi = col0; }
        if(dhi < bv){ bv = dhi; bi = col0+1; }
      }
      #pragma unroll
      for(int o=8;o;o>>=1){
        float ov = __shfl_xor_sync(0xffffffffu, bv, o);
        int   oi = __shfl_xor_sync(0xffffffffu, bi, o);
        if(ov < bv || (ov == bv && oi < bi)){ bv = ov; bi = oi; }
      }
      if(tx == 0){
        // later chunks have strictly larger indices -> strict < keeps
        // first-min-index semantics
        if(bv < sbv[row]){ sbv[row] = bv; sidx[row] = bi; }
      }
    }
    // no extra sync needed: next chunk's writes hit As/Bs which the
    // epilogue never reads; per-row smem best has a single writer.
  }

  __syncthreads();   // sidx final

  float* ip = idxdst ? idxdst : g_idxf;
  if(tid < 128)
    ip[(size_t)stage*MTOK + rowbase + tid] = (float)sidx[tid];

  // update phase: 2 threads per token, 128 cols each
  float loc = 0.f;
  {
    int row = tid >> 1, seg = tid & 1;
    int bin = sidx[row];
    const float4* q4 = (const float4*)(cbr + (size_t)bin*DCC + seg*128);
    float4* r4  = (float4*)(g_res   + (size_t)(rowbase+row)*DCC + seg*128);
    float4* qt4 = (float4*)(g_quant + (size_t)(rowbase+row)*DCC + seg*128);
    #pragma unroll
    for(int i=0;i<32;i++){
      float4 q = q4[i], r = r4[i], qt = qt4[i];
      float4 nr; nr.x=r.x-q.x; nr.y=r.y-q.y; nr.z=r.z-q.z; nr.w=r.w-q.w;
      r4[i] = nr;
      float4 nq; nq.x=qt.x+q.x; nq.y=qt.y+q.y; nq.z=qt.z+q.z; nq.w=qt.w+q.w;
      qt4[i] = nq;
      loc += nr.x*nr.x + nr.y*nr.y + nr.z*nr.z + nr.w*nr.w;
    }
  }
  #pragma unroll
  for(int o=16;o;o>>=1) loc += __shfl_xor_sync(0xffffffffu, loc, o);
  if(!lane) sred[wid] = loc;
  __syncthreads();
  if(tid < 8){
    float v = sred[tid];
    #pragma unroll
    for(int o=4;o;o>>=1) v += __shfl_xor_sync(0xffu, v, o);
    if(!tid) g_cpart[stage*512 + blockIdx.x] = v;
  }
}

// ---------------------------------------------------------------------------
__global__ void finalize_kernel(float* __restrict__ loss_dst){
  __shared__ float sr[512];
  int t = threadIdx.x;
  float s = 0.f;
  for(int k=t; k<NQ*512; k+=512) s += g_cpart[k];
  sr[t] = s; __syncthreads();
  for(int o=256;o;o>>=1){ if(t<o) sr[t]+=sr[t+o]; __syncthreads(); }
  if(!t) *loss_dst = 0.1f * sr[0] * (1.0f/((float)MTOK*(float)DCC));
}

__global__ void fill_kernel(float* __restrict__ p, int n){
  int i = blockIdx.x*256 + threadIdx.x;
  if(i < n) p[i] = 0.f;
}

// ---------------------------------------------------------------------------
extern "C" void kernel_launch(void* const* d_in, const int* in_sizes, int n_in,
                              void* d_out, int out_size){
  const float* x     = (const float*)d_in[0];
  const float* in_w  = (const float*)d_in[1];
  const float* in_b  = (const float*)d_in[2];
  const float* out_w = (const float*)d_in[3];
  const float* out_b = (const float*)d_in[4];
  const float* cb    = (const float*)d_in[5];
  float* out = (float*)d_out;

  if(out_size < OUTE){
    if(out_size > 0)
      fill_kernel<<<(out_size + 255)/256, 256>>>(out, out_size);
    return;
  }

  e2_kernel<<<NQ*NB/8, 256>>>(cb);

  gemm_kernel<<<dim3(MTOK/64, DCC/128), 256>>>(x, in_w, in_b, nullptr,
                                               DCC, DIN, 1);

  float* idxdst = (out_size >= OUTE + IDXE) ? (out + OUTE) : nullptr;
  for(int s=0; s<NQ; s++)
    stage_kernel<<<MTOK/128, 256>>>(cb + (size_t)s*NB*DCC, idxdst, s);

  gemm_kernel<<<dim3(MTOK/64, DIN/128), 256>>>(nullptr, out_w, out_b, out,
                                               DIN, DCC, 0);

  int written = OUTE;
  if(out_size >= OUTE + IDXE) written = OUTE + IDXE;
  if(out_size > written){
    finalize_kernel<<<1, 512>>>(out + written);
    written += 1;
  }
  if(out_size > written){
    int n = out_size - written;
    fill_kernel<<<(n + 255)/256, 256>>>(out + written, n);
  }
}